// round 2
// baseline (speedup 1.0000x reference)
#include <cuda_runtime.h>
#include <cuda_bf16.h>
#include <math.h>

// Problem dims
#define BB 32
#define TT 120
#define GG 25
#define DD 256
#define HH 8
#define HDD 32
#define BT (BB*TT)          // 3840
#define MROWS (BB*TT*GG)    // 96000
#define SZ ((size_t)MROWS*DD)

// Scratch (device globals; no allocation allowed)
__device__ float g_buf0[SZ]; // h, then att
__device__ float g_buf1[SZ]; // Q, then xatt
__device__ float g_buf2[SZ]; // K, then x1
__device__ float g_buf3[SZ]; // V, then fc

// ---------------------------------------------------------------------------
// 1) adjacency aggregation: h[b,t,g,d] = sum_n A[g,n] * x[b,t,n,d]
// ---------------------------------------------------------------------------
__global__ void __launch_bounds__(256) adj_kernel(const float* __restrict__ x,
                                                  const float* __restrict__ Adj,
                                                  float* __restrict__ h)
{
    __shared__ float As[GG*GG];
    int bt = blockIdx.x;
    int d  = threadIdx.x;
    for (int i = threadIdx.x; i < GG*GG; i += 256) As[i] = Adj[i];
    __syncthreads();

    const float* xp = x + (size_t)bt * GG * DD + d;
    float xr[GG];
#pragma unroll
    for (int n = 0; n < GG; n++) xr[n] = xp[(size_t)n * DD];

    float* hp = h + (size_t)bt * GG * DD + d;
#pragma unroll
    for (int g = 0; g < GG; g++) {
        float acc = 0.f;
#pragma unroll
        for (int n = 0; n < GG; n++) acc = fmaf(As[g*GG + n], xr[n], acc);
        hp[(size_t)g * DD] = acc;
    }
}

// ---------------------------------------------------------------------------
// 2) SGEMM: C[M,256] = A[M,256] * W[256,256]^T + bias, optional ReLU
//    BM=128, BN=128, BK=16, 256 threads, 8x8 per thread.
//    M = 96000 (divisible by 128), N = 256 (grid.y = 2).
// ---------------------------------------------------------------------------
__global__ void __launch_bounds__(256) sgemm_kernel(const float* __restrict__ A,
                                                    const float* __restrict__ W,
                                                    const float* __restrict__ bias,
                                                    float* __restrict__ C,
                                                    int relu)
{
    __shared__ float As[16][128];
    __shared__ float Bs[16][128];

    const int tid = threadIdx.x;
    const int tx  = tid & 15;        // 0..15 -> col group
    const int ty  = tid >> 4;        // 0..15 -> row group
    const size_t m0 = (size_t)blockIdx.x * 128;
    const int    n0 = blockIdx.y * 128;

    const int lrow = tid >> 2;       // 0..63
    const int lk4  = (tid & 3) * 4;  // 0,4,8,12

    const float* Ap = A + (m0 + lrow) * 256 + lk4;
    const float* Wp = W + (size_t)(n0 + lrow) * 256 + lk4;

    float c[8][8];
#pragma unroll
    for (int i = 0; i < 8; i++)
#pragma unroll
        for (int j = 0; j < 8; j++) c[i][j] = 0.f;

    for (int k0 = 0; k0 < 256; k0 += 16) {
        float4 a0 = *(const float4*)(Ap + k0);
        float4 a1 = *(const float4*)(Ap + (size_t)64*256 + k0);
        float4 b0 = *(const float4*)(Wp + k0);
        float4 b1 = *(const float4*)(Wp + (size_t)64*256 + k0);
        if (k0) __syncthreads();
        As[lk4+0][lrow] = a0.x; As[lk4+1][lrow] = a0.y;
        As[lk4+2][lrow] = a0.z; As[lk4+3][lrow] = a0.w;
        As[lk4+0][lrow+64] = a1.x; As[lk4+1][lrow+64] = a1.y;
        As[lk4+2][lrow+64] = a1.z; As[lk4+3][lrow+64] = a1.w;
        Bs[lk4+0][lrow] = b0.x; Bs[lk4+1][lrow] = b0.y;
        Bs[lk4+2][lrow] = b0.z; Bs[lk4+3][lrow] = b0.w;
        Bs[lk4+0][lrow+64] = b1.x; Bs[lk4+1][lrow+64] = b1.y;
        Bs[lk4+2][lrow+64] = b1.z; Bs[lk4+3][lrow+64] = b1.w;
        __syncthreads();

#pragma unroll
        for (int kk = 0; kk < 16; kk++) {
            float a[8], b[8];
            *(float4*)(a)     = *(const float4*)&As[kk][ty*8];
            *(float4*)(a + 4) = *(const float4*)&As[kk][ty*8 + 4];
            *(float4*)(b)     = *(const float4*)&Bs[kk][tx*8];
            *(float4*)(b + 4) = *(const float4*)&Bs[kk][tx*8 + 4];
#pragma unroll
            for (int i = 0; i < 8; i++)
#pragma unroll
                for (int j = 0; j < 8; j++)
                    c[i][j] = fmaf(a[i], b[j], c[i][j]);
        }
    }

    // epilogue: bias (+ReLU) and store
    float bv[8];
#pragma unroll
    for (int j = 0; j < 8; j++) bv[j] = bias[n0 + tx*8 + j];

#pragma unroll
    for (int i = 0; i < 8; i++) {
        size_t row = m0 + ty*8 + i;
        float* cp = C + row * 256 + n0 + tx*8;
#pragma unroll
        for (int j4 = 0; j4 < 2; j4++) {
            float4 v;
            float v0 = c[i][j4*4+0] + bv[j4*4+0];
            float v1 = c[i][j4*4+1] + bv[j4*4+1];
            float v2 = c[i][j4*4+2] + bv[j4*4+2];
            float v3 = c[i][j4*4+3] + bv[j4*4+3];
            if (relu) {
                v0 = fmaxf(v0, 0.f); v1 = fmaxf(v1, 0.f);
                v2 = fmaxf(v2, 0.f); v3 = fmaxf(v3, 0.f);
            }
            v.x = v0; v.y = v1; v.z = v2; v.w = v3;
            *(float4*)(cp + j4*4) = v;
        }
    }
}

// ---------------------------------------------------------------------------
// 3) attention per (b,t):
//    scores[g,h1,h2] = dot(Q[g,h1,:], K[g,h2,:]) / sqrt(HD)
//    w = softmax over g  (reference's dim=1 quirk)
//    att[g, h1*HD+dd] = sum_h2 w[g,h1,h2] * V[g, h2*HD+dd]
// ---------------------------------------------------------------------------
__global__ void __launch_bounds__(256) attn_kernel(const float* __restrict__ Q,
                                                   const float* __restrict__ K,
                                                   const float* __restrict__ V,
                                                   float* __restrict__ att)
{
    __shared__ float buf[GG][DD];      // K, then V (25.6 KB)
    __shared__ float w_s[GG][HH*HH];   // scores / weights (6.4 KB)

    const int bt = blockIdx.x;
    const size_t base = (size_t)bt * GG * DD;
    const int tid = threadIdx.x;
    const float scale = 0.1767766952966369f; // 1/sqrt(32)

    // load K
    for (int i = tid; i < GG*DD; i += 256) buf[i >> 8][i & 255] = K[base + i];
    __syncthreads();

    // scores (Q from gmem/L1, K from smem)
    for (int idx = tid; idx < GG*HH*HH; idx += 256) {
        int g  = idx >> 6;
        int h1 = (idx >> 3) & 7;
        int h2 = idx & 7;
        const float* qp = Q + base + g*DD + h1*HDD;
        const float* kp = &buf[g][h2*HDD];
        float acc = 0.f;
#pragma unroll
        for (int k = 0; k < HDD; k++) acc = fmaf(qp[k], kp[k], acc);
        w_s[g][h1*8 + h2] = acc * scale;
    }
    __syncthreads();

    // load V (overwrites K region); softmax threads touch only w_s, so no race
    for (int i = tid; i < GG*DD; i += 256) {
        buf[i >> 8][i & 255] = V[base + i];
    }
    if (tid < 64) {
        float mx = -1e30f;
#pragma unroll
        for (int g = 0; g < GG; g++) mx = fmaxf(mx, w_s[g][tid]);
        float s = 0.f;
#pragma unroll
        for (int g = 0; g < GG; g++) {
            float e = expf(w_s[g][tid] - mx);
            w_s[g][tid] = e;
            s += e;
        }
        float inv = 1.f / s;
#pragma unroll
        for (int g = 0; g < GG; g++) w_s[g][tid] *= inv;
    }
    __syncthreads();

    // att
    for (int idx = tid; idx < GG*DD; idx += 256) {
        int g  = idx >> 8;
        int d  = idx & 255;
        int h1 = d >> 5;
        int dd = d & 31;
        float acc = 0.f;
#pragma unroll
        for (int h2 = 0; h2 < 8; h2++)
            acc = fmaf(w_s[g][h1*8 + h2], buf[g][h2*32 + dd], acc);
        att[base + idx] = acc;
    }
}

// ---------------------------------------------------------------------------
// 4) residual + layernorm (ddof=1): out = alpha*(z-mu)/(std+eps) + beta
// ---------------------------------------------------------------------------
__global__ void __launch_bounds__(256) addnorm_kernel(const float* __restrict__ a,
                                                      const float* __restrict__ b,
                                                      const float* __restrict__ alpha,
                                                      const float* __restrict__ beta,
                                                      float* __restrict__ out)
{
    __shared__ float red[8];
    const size_t row = blockIdx.x;
    const int d = threadIdx.x;
    const int lane = d & 31, warp = d >> 5;

    float z = a[row*256 + d] + b[row*256 + d];

    // sum
    float s = z;
#pragma unroll
    for (int o = 16; o > 0; o >>= 1) s += __shfl_xor_sync(0xffffffffu, s, o);
    if (lane == 0) red[warp] = s;
    __syncthreads();
    float tot = red[0] + red[1] + red[2] + red[3] + red[4] + red[5] + red[6] + red[7];
    float mu = tot * (1.f / 256.f);
    float dz = z - mu;

    // sum of squares of deviations
    float s2 = dz * dz;
#pragma unroll
    for (int o = 16; o > 0; o >>= 1) s2 += __shfl_xor_sync(0xffffffffu, s2, o);
    __syncthreads();
    if (lane == 0) red[warp] = s2;
    __syncthreads();
    float tot2 = red[0] + red[1] + red[2] + red[3] + red[4] + red[5] + red[6] + red[7];
    float sd = sqrtf(tot2 * (1.f / 255.f));

    out[row*256 + d] = alpha[d] * dz / (sd + 1e-6f) + beta[d];
}

// ---------------------------------------------------------------------------
extern "C" void kernel_launch(void* const* d_in, const int* in_sizes, int n_in,
                              void* d_out, int out_size)
{
    const float* x    = (const float*)d_in[0];
    const float* Adj  = (const float*)d_in[1];
    const float* Wq   = (const float*)d_in[2];
    const float* bq   = (const float*)d_in[3];
    const float* Wk   = (const float*)d_in[4];
    const float* bk   = (const float*)d_in[5];
    const float* Wv   = (const float*)d_in[6];
    const float* bv   = (const float*)d_in[7];
    const float* Wo   = (const float*)d_in[8];
    const float* bo   = (const float*)d_in[9];
    const float* Wfc  = (const float*)d_in[10];
    const float* bfc  = (const float*)d_in[11];
    const float* alpha= (const float*)d_in[12];
    const float* beta = (const float*)d_in[13];
    float* out = (float*)d_out;

    float *h, *q, *k, *v;
    cudaGetSymbolAddress((void**)&h, g_buf0);
    cudaGetSymbolAddress((void**)&q, g_buf1);
    cudaGetSymbolAddress((void**)&k, g_buf2);
    cudaGetSymbolAddress((void**)&v, g_buf3);

    dim3 gemm_grid(MROWS / 128, 2);

    // 1) h = A @ x (per b,t)
    adj_kernel<<<BT, 256>>>(x, Adj, h);
    // 2) Q,K,V = h @ W^T + b    (kept in [B,T,G,D] layout)
    sgemm_kernel<<<gemm_grid, 256>>>(h, Wq, bq, q, 0);
    sgemm_kernel<<<gemm_grid, 256>>>(h, Wk, bk, k, 0);
    sgemm_kernel<<<gemm_grid, 256>>>(h, Wv, bv, v, 0);
    // 3) attention (softmax over G) -> att into buf0 (h dead)
    attn_kernel<<<BT, 256>>>(q, k, v, h);
    // 4) x_att = att @ Wo^T + bo -> buf1 (Q dead)
    sgemm_kernel<<<gemm_grid, 256>>>(h, Wo, bo, q, 0);
    // 5) x1 = norm(x + x_att) -> buf2 (K dead)
    addnorm_kernel<<<MROWS, 256>>>(x, q, alpha, beta, k);
    // 6) fc = relu(x1 @ Wfc^T + bfc) -> buf3 (V dead)
    sgemm_kernel<<<gemm_grid, 256>>>(k, Wfc, bfc, v, 1);
    // 7) out = norm(x1 + fc)
    addnorm_kernel<<<MROWS, 256>>>(k, v, alpha, beta, out);
}

// round 8
// speedup vs baseline: 1.5526x; 1.5526x over previous
#include <cuda_runtime.h>
#include <cuda_bf16.h>
#include <math.h>

// Problem dims
#define BB 32
#define TT 120
#define GG 25
#define DD 256
#define HH 8
#define HDD 32
#define BT (BB*TT)          // 3840
#define MROWS (BB*TT*GG)    // 96000
#define SZ ((size_t)MROWS*DD)

// Scratch (device globals; no allocation allowed)
__device__ float g_buf0[SZ]; // h, then att
__device__ float g_buf1[SZ]; // Q, then xatt
__device__ float g_buf2[SZ]; // K, then x1
__device__ float g_buf3[SZ]; // V, then fc

// Split-bf16 weights: 5 matrices of 256x256
__device__ __nv_bfloat16 g_whi[5][DD*DD];
__device__ __nv_bfloat16 g_wlo[5][DD*DD];

__device__ __forceinline__ unsigned smem_u32(const void* p) {
    unsigned a;
    asm("{ .reg .u64 t; cvta.to.shared.u64 t, %1; cvt.u32.u64 %0, t; }" : "=r"(a) : "l"(p));
    return a;
}

__device__ __forceinline__ void ldm_x4(unsigned& r0, unsigned& r1, unsigned& r2, unsigned& r3,
                                       unsigned addr) {
    asm volatile("ldmatrix.sync.aligned.m8n8.x4.shared.b16 {%0,%1,%2,%3}, [%4];"
                 : "=r"(r0), "=r"(r1), "=r"(r2), "=r"(r3) : "r"(addr));
}
__device__ __forceinline__ void ldm_x2(unsigned& r0, unsigned& r1, unsigned addr) {
    asm volatile("ldmatrix.sync.aligned.m8n8.x2.shared.b16 {%0,%1}, [%2];"
                 : "=r"(r0), "=r"(r1) : "r"(addr));
}
__device__ __forceinline__ void mma_bf16(float* d, const unsigned* a, const unsigned* b) {
    asm volatile("mma.sync.aligned.m16n8k16.row.col.f32.bf16.bf16.f32 "
                 "{%0,%1,%2,%3}, {%4,%5,%6,%7}, {%8,%9}, {%0,%1,%2,%3};"
                 : "+f"(d[0]), "+f"(d[1]), "+f"(d[2]), "+f"(d[3])
                 : "r"(a[0]), "r"(a[1]), "r"(a[2]), "r"(a[3]), "r"(b[0]), "r"(b[1]));
}

// ===========================================================================
// 0) weight split prep: W fp32 -> (hi, lo) bf16
// ===========================================================================
__global__ void __launch_bounds__(256) wprep_kernel(const float* __restrict__ w0,
                                                    const float* __restrict__ w1,
                                                    const float* __restrict__ w2,
                                                    const float* __restrict__ w3,
                                                    const float* __restrict__ w4)
{
    const float* ws[5] = {w0, w1, w2, w3, w4};
    int wi = blockIdx.y;
    int idx = blockIdx.x * 256 + threadIdx.x;   // grid.x = 256 -> 65536 elems
    float v = ws[wi][idx];
    __nv_bfloat16 h = __float2bfloat16(v);
    g_whi[wi][idx] = h;
    g_wlo[wi][idx] = __float2bfloat16(v - __bfloat162float(h));
}

// ===========================================================================
// 1) adjacency aggregation: h[b,t,g,d] = sum_n A[g,n] * x[b,t,n,d]
// ===========================================================================
__global__ void __launch_bounds__(256) adj_kernel(const float* __restrict__ x,
                                                  const float* __restrict__ Adj,
                                                  float* __restrict__ h)
{
    __shared__ float As[GG*GG];
    int bt = blockIdx.x;
    int d  = threadIdx.x;
    for (int i = threadIdx.x; i < GG*GG; i += 256) As[i] = Adj[i];
    __syncthreads();

    const float* xp = x + (size_t)bt * GG * DD + d;
    float xr[GG];
#pragma unroll
    for (int n = 0; n < GG; n++) xr[n] = xp[(size_t)n * DD];

    float* hp = h + (size_t)bt * GG * DD + d;
#pragma unroll
    for (int g = 0; g < GG; g++) {
        float acc = 0.f;
#pragma unroll
        for (int n = 0; n < GG; n++) acc = fmaf(As[g*GG + n], xr[n], acc);
        hp[(size_t)g * DD] = acc;
    }
}

// ===========================================================================
// 2) mma.sync bf16-split GEMM: C[M,256] = A[M,256] @ W[256,256]^T + bias (+relu)
//    BM=128, BN=128, BK=32; 8 warps, warp tile 64x32.
//    C = Ah*Bh + Ah*Bl + Al*Bh, fp32 accumulate.
// ===========================================================================
#define ROWB 80   // smem row pitch in bytes (32 bf16 data + 16B pad)

__global__ void __launch_bounds__(256, 2) gemm_mma_kernel(const float* __restrict__ A,
                                                          const __nv_bfloat16* __restrict__ Whi,
                                                          const __nv_bfloat16* __restrict__ Wlo,
                                                          const float* __restrict__ bias,
                                                          float* __restrict__ C,
                                                          int relu)
{
    __shared__ __nv_bfloat16 sAh[128][40];
    __shared__ __nv_bfloat16 sAl[128][40];
    __shared__ __nv_bfloat16 sBh[128][40];
    __shared__ __nv_bfloat16 sBl[128][40];

    const int tid  = threadIdx.x;
    const int wid  = tid >> 5;
    const int lane = tid & 31;
    const size_t m0 = (size_t)blockIdx.x * 128;
    const int    n0 = blockIdx.y * 128;

    const int warp_m = (wid >> 2) * 64;   // 0 or 64
    const int warp_n = (wid & 3) * 32;    // 0,32,64,96

    const unsigned sAh_b = smem_u32(sAh);
    const unsigned sAl_b = smem_u32(sAl);
    const unsigned sBh_b = smem_u32(sBh);
    const unsigned sBl_b = smem_u32(sBl);

    float acc[4][4][4];
#pragma unroll
    for (int i = 0; i < 4; i++)
#pragma unroll
        for (int j = 0; j < 4; j++)
#pragma unroll
            for (int r = 0; r < 4; r++) acc[i][j][r] = 0.f;

    // staging indices: each thread loads 16 contiguous elems of one row
    const int srow = tid >> 1;
    const int shalf = tid & 1;          // which 16-elem half of the 32-wide chunk

    // ldmatrix lane addressing
    const unsigned a_row = warp_m + (lane & 15);
    const unsigned a_byt = (unsigned)(lane >> 4) * 16;
    const unsigned b_row = warp_n + (lane & 7);
    const unsigned b_byt = (unsigned)((lane >> 3) & 1) * 16;

    for (int c = 0; c < 8; c++) {
        // ---- stage A: 128x32 fp32 -> hi/lo bf16
        {
            const float* ap = A + (m0 + srow) * 256 + c * 32 + shalf * 16;
            float4 v0 = *(const float4*)(ap + 0);
            float4 v1 = *(const float4*)(ap + 4);
            float4 v2 = *(const float4*)(ap + 8);
            float4 v3 = *(const float4*)(ap + 12);
            float vv[16] = {v0.x,v0.y,v0.z,v0.w, v1.x,v1.y,v1.z,v1.w,
                            v2.x,v2.y,v2.z,v2.w, v3.x,v3.y,v3.z,v3.w};
            union { uint4 q[2]; __nv_bfloat16 b[16]; } hi, lo;
#pragma unroll
            for (int j = 0; j < 16; j++) {
                __nv_bfloat16 h = __float2bfloat16(vv[j]);
                hi.b[j] = h;
                lo.b[j] = __float2bfloat16(vv[j] - __bfloat162float(h));
            }
            uint4* dh = (uint4*)&sAh[srow][shalf * 16];
            uint4* dl = (uint4*)&sAl[srow][shalf * 16];
            dh[0] = hi.q[0]; dh[1] = hi.q[1];
            dl[0] = lo.q[0]; dl[1] = lo.q[1];
        }
        // ---- stage B: 128x32 pre-split bf16
        {
            const __nv_bfloat16* bh = Whi + (size_t)(n0 + srow) * 256 + c * 32 + shalf * 16;
            const __nv_bfloat16* bl = Wlo + (size_t)(n0 + srow) * 256 + c * 32 + shalf * 16;
            uint4 h0 = ((const uint4*)bh)[0];
            uint4 h1 = ((const uint4*)bh)[1];
            uint4 l0 = ((const uint4*)bl)[0];
            uint4 l1 = ((const uint4*)bl)[1];
            uint4* dh = (uint4*)&sBh[srow][shalf * 16];
            uint4* dl = (uint4*)&sBl[srow][shalf * 16];
            dh[0] = h0; dh[1] = h1;
            dl[0] = l0; dl[1] = l1;
        }
        __syncthreads();

        // ---- compute: 2 k-steps of 16
#pragma unroll
        for (int ks = 0; ks < 2; ks++) {
            const unsigned koff = (unsigned)ks * 32;
            unsigned aH[4][4], aL[4][4], bH[4][2], bL[4][2];
#pragma unroll
            for (int mt = 0; mt < 4; mt++) {
                unsigned ra = (a_row + mt * 16) * ROWB + koff + a_byt;
                ldm_x4(aH[mt][0], aH[mt][1], aH[mt][2], aH[mt][3], sAh_b + ra);
                ldm_x4(aL[mt][0], aL[mt][1], aL[mt][2], aL[mt][3], sAl_b + ra);
            }
#pragma unroll
            for (int nt = 0; nt < 4; nt++) {
                unsigned rb = (b_row + nt * 8) * ROWB + koff + b_byt;
                ldm_x2(bH[nt][0], bH[nt][1], sBh_b + rb);
                ldm_x2(bL[nt][0], bL[nt][1], sBl_b + rb);
            }
#pragma unroll
            for (int mt = 0; mt < 4; mt++)
#pragma unroll
                for (int nt = 0; nt < 4; nt++) {
                    mma_bf16(acc[mt][nt], aH[mt], bH[nt]);
                    mma_bf16(acc[mt][nt], aH[mt], bL[nt]);
                    mma_bf16(acc[mt][nt], aL[mt], bH[nt]);
                }
        }
        __syncthreads();
    }

    // ---- epilogue: bias (+relu), direct gmem store
    const int r0 = lane >> 2;
    const int cc = (lane & 3) * 2;
#pragma unroll
    for (int mt = 0; mt < 4; mt++) {
        size_t gm = m0 + warp_m + mt * 16;
#pragma unroll
        for (int nt = 0; nt < 4; nt++) {
            int gn = n0 + warp_n + nt * 8 + cc;
            float bx = bias[gn], by = bias[gn + 1];
            float2 p0, p1;
            p0.x = acc[mt][nt][0] + bx; p0.y = acc[mt][nt][1] + by;
            p1.x = acc[mt][nt][2] + bx; p1.y = acc[mt][nt][3] + by;
            if (relu) {
                p0.x = fmaxf(p0.x, 0.f); p0.y = fmaxf(p0.y, 0.f);
                p1.x = fmaxf(p1.x, 0.f); p1.y = fmaxf(p1.y, 0.f);
            }
            *(float2*)(C + (gm + r0)     * 256 + gn) = p0;
            *(float2*)(C + (gm + r0 + 8) * 256 + gn) = p1;
        }
    }
}

// ===========================================================================
// 3) attention per (b,t)  (softmax over G — reference's dim=1 quirk)
// ===========================================================================
__global__ void __launch_bounds__(256) attn_kernel(const float* __restrict__ Q,
                                                   const float* __restrict__ K,
                                                   const float* __restrict__ V,
                                                   float* __restrict__ att)
{
    __shared__ float buf[GG][DD];
    __shared__ float w_s[GG][HH*HH];

    const int bt = blockIdx.x;
    const size_t base = (size_t)bt * GG * DD;
    const int tid = threadIdx.x;
    const float scale = 0.1767766952966369f; // 1/sqrt(32)

    for (int i = tid; i < GG*DD; i += 256) buf[i >> 8][i & 255] = K[base + i];
    __syncthreads();

    for (int idx = tid; idx < GG*HH*HH; idx += 256) {
        int g  = idx >> 6;
        int h1 = (idx >> 3) & 7;
        int h2 = idx & 7;
        const float* qp = Q + base + g*DD + h1*HDD;
        const float* kp = &buf[g][h2*HDD];
        float acc = 0.f;
#pragma unroll
        for (int k = 0; k < HDD; k++) acc = fmaf(qp[k], kp[k], acc);
        w_s[g][h1*8 + h2] = acc * scale;
    }
    __syncthreads();

    for (int i = tid; i < GG*DD; i += 256) buf[i >> 8][i & 255] = V[base + i];
    if (tid < 64) {
        float mx = -1e30f;
#pragma unroll
        for (int g = 0; g < GG; g++) mx = fmaxf(mx, w_s[g][tid]);
        float s = 0.f;
#pragma unroll
        for (int g = 0; g < GG; g++) {
            float e = expf(w_s[g][tid] - mx);
            w_s[g][tid] = e;
            s += e;
        }
        float inv = 1.f / s;
#pragma unroll
        for (int g = 0; g < GG; g++) w_s[g][tid] *= inv;
    }
    __syncthreads();

    for (int idx = tid; idx < GG*DD; idx += 256) {
        int g  = idx >> 8;
        int d  = idx & 255;
        int h1 = d >> 5;
        int dd = d & 31;
        float acc = 0.f;
#pragma unroll
        for (int h2 = 0; h2 < 8; h2++)
            acc = fmaf(w_s[g][h1*8 + h2], buf[g][h2*32 + dd], acc);
        att[base + idx] = acc;
    }
}

// ===========================================================================
// 4) residual + layernorm (ddof=1)
// ===========================================================================
__global__ void __launch_bounds__(256) addnorm_kernel(const float* __restrict__ a,
                                                      const float* __restrict__ b,
                                                      const float* __restrict__ alpha,
                                                      const float* __restrict__ beta,
                                                      float* __restrict__ out)
{
    __shared__ float red[8];
    const size_t row = blockIdx.x;
    const int d = threadIdx.x;
    const int lane = d & 31, warp = d >> 5;

    float z = a[row*256 + d] + b[row*256 + d];

    float s = z;
#pragma unroll
    for (int o = 16; o > 0; o >>= 1) s += __shfl_xor_sync(0xffffffffu, s, o);
    if (lane == 0) red[warp] = s;
    __syncthreads();
    float tot = red[0] + red[1] + red[2] + red[3] + red[4] + red[5] + red[6] + red[7];
    float mu = tot * (1.f / 256.f);
    float dz = z - mu;

    float s2 = dz * dz;
#pragma unroll
    for (int o = 16; o > 0; o >>= 1) s2 += __shfl_xor_sync(0xffffffffu, s2, o);
    __syncthreads();
    if (lane == 0) red[warp] = s2;
    __syncthreads();
    float tot2 = red[0] + red[1] + red[2] + red[3] + red[4] + red[5] + red[6] + red[7];
    float sd = sqrtf(tot2 * (1.f / 255.f));

    out[row*256 + d] = alpha[d] * dz / (sd + 1e-6f) + beta[d];
}

// ===========================================================================
extern "C" void kernel_launch(void* const* d_in, const int* in_sizes, int n_in,
                              void* d_out, int out_size)
{
    const float* x    = (const float*)d_in[0];
    const float* Adj  = (const float*)d_in[1];
    const float* Wq   = (const float*)d_in[2];
    const float* bq   = (const float*)d_in[3];
    const float* Wk   = (const float*)d_in[4];
    const float* bk   = (const float*)d_in[5];
    const float* Wv   = (const float*)d_in[6];
    const float* bv   = (const float*)d_in[7];
    const float* Wo   = (const float*)d_in[8];
    const float* bo   = (const float*)d_in[9];
    const float* Wfc  = (const float*)d_in[10];
    const float* bfc  = (const float*)d_in[11];
    const float* alpha= (const float*)d_in[12];
    const float* beta = (const float*)d_in[13];
    float* out = (float*)d_out;

    float *h, *q, *k, *v;
    cudaGetSymbolAddress((void**)&h, g_buf0);
    cudaGetSymbolAddress((void**)&q, g_buf1);
    cudaGetSymbolAddress((void**)&k, g_buf2);
    cudaGetSymbolAddress((void**)&v, g_buf3);
    __nv_bfloat16 *whi, *wlo;
    cudaGetSymbolAddress((void**)&whi, g_whi);
    cudaGetSymbolAddress((void**)&wlo, g_wlo);

    dim3 ggrid(MROWS / 128, 2);

    // 0) split weights to bf16 hi/lo  (order: q,k,v,o,fc)
    wprep_kernel<<<dim3(256, 5), 256>>>(Wq, Wk, Wv, Wo, Wfc);
    // 1) h = A @ x
    adj_kernel<<<BT, 256>>>(x, Adj, h);
    // 2) Q,K,V projections (mma.sync bf16-split)
    gemm_mma_kernel<<<ggrid, 256>>>(h, whi + 0*DD*DD, wlo + 0*DD*DD, bq, q, 0);
    gemm_mma_kernel<<<ggrid, 256>>>(h, whi + 1*DD*DD, wlo + 1*DD*DD, bk, k, 0);
    gemm_mma_kernel<<<ggrid, 256>>>(h, whi + 2*DD*DD, wlo + 2*DD*DD, bv, v, 0);
    // 3) attention -> att into buf0
    attn_kernel<<<BT, 256>>>(q, k, v, h);
    // 4) x_att = att @ Wo^T + bo -> buf1
    gemm_mma_kernel<<<ggrid, 256>>>(h, whi + 3*DD*DD, wlo + 3*DD*DD, bo, q, 0);
    // 5) x1 = norm(x + x_att) -> buf2
    addnorm_kernel<<<MROWS, 256>>>(x, q, alpha, beta, k);
    // 6) fc = relu(x1 @ Wfc^T + bfc) -> buf3
    gemm_mma_kernel<<<ggrid, 256>>>(k, whi + 4*DD*DD, wlo + 4*DD*DD, bfc, v, 1);
    // 7) out = norm(x1 + fc)
    addnorm_kernel<<<MROWS, 256>>>(k, v, alpha, beta, out);
}

// round 14
// speedup vs baseline: 1.8491x; 1.1910x over previous
#include <cuda_runtime.h>
#include <cuda_bf16.h>
#include <math.h>

// Problem dims
#define BB 32
#define TT 120
#define GG 25
#define DD 256
#define HH 8
#define HDD 32
#define BT (BB*TT)          // 3840
#define MROWS (BB*TT*GG)    // 96000
#define SZ ((size_t)MROWS*DD)

// Scratch (device globals; no allocation allowed)
__device__ float g_buf1[SZ]; // Q, then x_att
__device__ float g_buf2[SZ]; // K, then x1
__device__ float g_buf3[SZ]; // V, then fc
__device__ __nv_bfloat16 g_ahi[SZ]; // split-bf16 activation pair: h -> att -> x1
__device__ __nv_bfloat16 g_alo[SZ];

// Split-bf16 weights: 5 matrices of 256x256
__device__ __nv_bfloat16 g_whi[5][DD*DD];
__device__ __nv_bfloat16 g_wlo[5][DD*DD];

__device__ __forceinline__ unsigned smem_u32(const void* p) {
    unsigned a;
    asm("{ .reg .u64 t; cvta.to.shared.u64 t, %1; cvt.u32.u64 %0, t; }" : "=r"(a) : "l"(p));
    return a;
}
__device__ __forceinline__ void ldm_x4(unsigned& r0, unsigned& r1, unsigned& r2, unsigned& r3,
                                       unsigned addr) {
    asm volatile("ldmatrix.sync.aligned.m8n8.x4.shared.b16 {%0,%1,%2,%3}, [%4];"
                 : "=r"(r0), "=r"(r1), "=r"(r2), "=r"(r3) : "r"(addr));
}
__device__ __forceinline__ void ldm_x2(unsigned& r0, unsigned& r1, unsigned addr) {
    asm volatile("ldmatrix.sync.aligned.m8n8.x2.shared.b16 {%0,%1}, [%2];"
                 : "=r"(r0), "=r"(r1) : "r"(addr));
}
__device__ __forceinline__ void mma_bf16(float* d, const unsigned* a, const unsigned* b) {
    asm volatile("mma.sync.aligned.m16n8k16.row.col.f32.bf16.bf16.f32 "
                 "{%0,%1,%2,%3}, {%4,%5,%6,%7}, {%8,%9}, {%0,%1,%2,%3};"
                 : "+f"(d[0]), "+f"(d[1]), "+f"(d[2]), "+f"(d[3])
                 : "r"(a[0]), "r"(a[1]), "r"(a[2]), "r"(a[3]), "r"(b[0]), "r"(b[1]));
}
__device__ __forceinline__ void cp_async16(unsigned dst, const void* src) {
    asm volatile("cp.async.cg.shared.global [%0], [%1], 16;" :: "r"(dst), "l"(src));
}
__device__ __forceinline__ void cp_commit() {
    asm volatile("cp.async.commit_group;" ::: "memory");
}
__device__ __forceinline__ void cp_wait1() {
    asm volatile("cp.async.wait_group 1;" ::: "memory");
}
__device__ __forceinline__ void cp_wait0() {
    asm volatile("cp.async.wait_group 0;" ::: "memory");
}

// split helper
__device__ __forceinline__ void split_bf16(float v, __nv_bfloat16& hi, __nv_bfloat16& lo) {
    hi = __float2bfloat16(v);
    lo = __float2bfloat16(v - __bfloat162float(hi));
}

// ===========================================================================
// 0) weight split prep
// ===========================================================================
__global__ void __launch_bounds__(256) wprep_kernel(const float* __restrict__ w0,
                                                    const float* __restrict__ w1,
                                                    const float* __restrict__ w2,
                                                    const float* __restrict__ w3,
                                                    const float* __restrict__ w4)
{
    const float* ws[5] = {w0, w1, w2, w3, w4};
    int wi = blockIdx.y;
    int idx = blockIdx.x * 256 + threadIdx.x;
    float v = ws[wi][idx];
    __nv_bfloat16 h, l;
    split_bf16(v, h, l);
    g_whi[wi][idx] = h;
    g_wlo[wi][idx] = l;
}

// ===========================================================================
// 1) adjacency aggregation: writes h directly as split bf16
// ===========================================================================
__global__ void __launch_bounds__(256) adj_kernel(const float* __restrict__ x,
                                                  const float* __restrict__ Adj)
{
    __shared__ float As[GG*GG];
    int bt = blockIdx.x;
    int d  = threadIdx.x;
    for (int i = threadIdx.x; i < GG*GG; i += 256) As[i] = Adj[i];
    __syncthreads();

    const float* xp = x + (size_t)bt * GG * DD + d;
    float xr[GG];
#pragma unroll
    for (int n = 0; n < GG; n++) xr[n] = xp[(size_t)n * DD];

    size_t base = (size_t)bt * GG * DD + d;
#pragma unroll
    for (int g = 0; g < GG; g++) {
        float acc = 0.f;
#pragma unroll
        for (int n = 0; n < GG; n++) acc = fmaf(As[g*GG + n], xr[n], acc);
        __nv_bfloat16 h, l;
        split_bf16(acc, h, l);
        g_ahi[base + (size_t)g * DD] = h;
        g_alo[base + (size_t)g * DD] = l;
    }
}

// ===========================================================================
// 2) double-buffered cp.async mma GEMM
//    A given as split bf16 (hi/lo). C = Ah*Bh + Ah*Bl + Al*Bh + bias (+relu)
//    BM=128, BN=128, BK=32; smem: 2 stages x 4 tiles x (128 rows x 80B) = 80KB
// ===========================================================================
#define ROWB 80
#define TILE_B (128*ROWB)        // 10240
#define STAGE_B (4*TILE_B)       // 40960
#define GSMEM (2*STAGE_B)        // 81920

__global__ void __launch_bounds__(256, 2) gemm2_kernel(const __nv_bfloat16* __restrict__ Ahi,
                                                       const __nv_bfloat16* __restrict__ Alo,
                                                       const __nv_bfloat16* __restrict__ Whi,
                                                       const __nv_bfloat16* __restrict__ Wlo,
                                                       const float* __restrict__ bias,
                                                       float* __restrict__ C,
                                                       int relu)
{
    extern __shared__ __nv_bfloat16 dynsm[];
    const unsigned sb = smem_u32(dynsm);

    const int tid  = threadIdx.x;
    const int wid  = tid >> 5;
    const int lane = tid & 31;
    const size_t m0 = (size_t)blockIdx.x * 128;
    const int    n0 = blockIdx.y * 128;

    const int warp_m = (wid >> 2) * 64;
    const int warp_n = (wid & 3) * 32;

    float acc[4][4][4];
#pragma unroll
    for (int i = 0; i < 4; i++)
#pragma unroll
        for (int j = 0; j < 4; j++)
#pragma unroll
            for (int r = 0; r < 4; r++) acc[i][j][r] = 0.f;

    const int srow  = tid >> 1;
    const int shalf = tid & 1;

    // gmem base offsets for this thread's staged row
    const __nv_bfloat16* a_hi = Ahi + (m0 + srow) * 256 + shalf * 16;
    const __nv_bfloat16* a_lo = Alo + (m0 + srow) * 256 + shalf * 16;
    const __nv_bfloat16* b_hi = Whi + (size_t)(n0 + srow) * 256 + shalf * 16;
    const __nv_bfloat16* b_lo = Wlo + (size_t)(n0 + srow) * 256 + shalf * 16;
    const unsigned drow = (unsigned)(srow * ROWB + shalf * 32);

    // ldmatrix lane addressing
    const unsigned a_row = warp_m + (lane & 15);
    const unsigned a_byt = (unsigned)(lane >> 4) * 16;
    const unsigned b_row = warp_n + (lane & 7);
    const unsigned b_byt = (unsigned)((lane >> 3) & 1) * 16;

#define STAGE_FILL(c, s) do {                                                  \
        unsigned d0 = sb + (unsigned)(s) * STAGE_B + drow;                     \
        const __nv_bfloat16* s0 = a_hi + (c) * 32;                             \
        cp_async16(d0,               s0);     cp_async16(d0 + 16,              s0 + 8); \
        const __nv_bfloat16* s1 = a_lo + (c) * 32;                             \
        cp_async16(d0 + TILE_B,      s1);     cp_async16(d0 + TILE_B + 16,     s1 + 8); \
        const __nv_bfloat16* s2 = b_hi + (c) * 32;                             \
        cp_async16(d0 + 2*TILE_B,    s2);     cp_async16(d0 + 2*TILE_B + 16,   s2 + 8); \
        const __nv_bfloat16* s3 = b_lo + (c) * 32;                             \
        cp_async16(d0 + 3*TILE_B,    s3);     cp_async16(d0 + 3*TILE_B + 16,   s3 + 8); \
        cp_commit();                                                           \
    } while (0)

    STAGE_FILL(0, 0);

    for (int c = 0; c < 8; c++) {
        if (c < 7) {
            STAGE_FILL(c + 1, (c + 1) & 1);
            cp_wait1();
        } else {
            cp_wait0();
        }
        __syncthreads();

        const unsigned st = sb + (unsigned)(c & 1) * STAGE_B;
#pragma unroll
        for (int ks = 0; ks < 2; ks++) {
            const unsigned koff = (unsigned)ks * 32;
            unsigned aH[4][4], aL[4][4], bH[4][2], bL[4][2];
#pragma unroll
            for (int mt = 0; mt < 4; mt++) {
                unsigned ra = st + (a_row + mt * 16) * ROWB + koff + a_byt;
                ldm_x4(aH[mt][0], aH[mt][1], aH[mt][2], aH[mt][3], ra);
                ldm_x4(aL[mt][0], aL[mt][1], aL[mt][2], aL[mt][3], ra + TILE_B);
            }
#pragma unroll
            for (int nt = 0; nt < 4; nt++) {
                unsigned rb = st + 2*TILE_B + (b_row + nt * 8) * ROWB + koff + b_byt;
                ldm_x2(bH[nt][0], bH[nt][1], rb);
                ldm_x2(bL[nt][0], bL[nt][1], rb + TILE_B);
            }
#pragma unroll
            for (int mt = 0; mt < 4; mt++)
#pragma unroll
                for (int nt = 0; nt < 4; nt++) {
                    mma_bf16(acc[mt][nt], aH[mt], bH[nt]);
                    mma_bf16(acc[mt][nt], aH[mt], bL[nt]);
                    mma_bf16(acc[mt][nt], aL[mt], bH[nt]);
                }
        }
        __syncthreads();
    }

    // epilogue
    const int r0 = lane >> 2;
    const int cc = (lane & 3) * 2;
#pragma unroll
    for (int mt = 0; mt < 4; mt++) {
        size_t gm = m0 + warp_m + mt * 16;
#pragma unroll
        for (int nt = 0; nt < 4; nt++) {
            int gn = n0 + warp_n + nt * 8 + cc;
            float bx = bias[gn], by = bias[gn + 1];
            float2 p0, p1;
            p0.x = acc[mt][nt][0] + bx; p0.y = acc[mt][nt][1] + by;
            p1.x = acc[mt][nt][2] + bx; p1.y = acc[mt][nt][3] + by;
            if (relu) {
                p0.x = fmaxf(p0.x, 0.f); p0.y = fmaxf(p0.y, 0.f);
                p1.x = fmaxf(p1.x, 0.f); p1.y = fmaxf(p1.y, 0.f);
            }
            *(float2*)(C + (gm + r0)     * 256 + gn) = p0;
            *(float2*)(C + (gm + r0 + 8) * 256 + gn) = p1;
        }
    }
#undef STAGE_FILL
}

// ===========================================================================
// 3) attention per (b,t); writes att as split bf16 into g_ahi/g_alo
// ===========================================================================
__global__ void __launch_bounds__(256) attn_kernel(const float* __restrict__ Q,
                                                   const float* __restrict__ K,
                                                   const float* __restrict__ V)
{
    __shared__ float buf[GG][DD];
    __shared__ float w_s[GG][HH*HH];

    const int bt = blockIdx.x;
    const size_t base = (size_t)bt * GG * DD;
    const int tid = threadIdx.x;
    const float scale = 0.1767766952966369f; // 1/sqrt(32)

    for (int i = tid; i < GG*DD; i += 256) buf[i >> 8][i & 255] = K[base + i];
    __syncthreads();

    for (int idx = tid; idx < GG*HH*HH; idx += 256) {
        int g  = idx >> 6;
        int h1 = (idx >> 3) & 7;
        int h2 = idx & 7;
        const float* qp = Q + base + g*DD + h1*HDD;
        const float* kp = &buf[g][h2*HDD];
        float acc = 0.f;
#pragma unroll
        for (int k = 0; k < HDD; k++) acc = fmaf(qp[k], kp[k], acc);
        w_s[g][h1*8 + h2] = acc * scale;
    }
    __syncthreads();

    for (int i = tid; i < GG*DD; i += 256) buf[i >> 8][i & 255] = V[base + i];
    if (tid < 64) {
        float mx = -1e30f;
#pragma unroll
        for (int g = 0; g < GG; g++) mx = fmaxf(mx, w_s[g][tid]);
        float s = 0.f;
#pragma unroll
        for (int g = 0; g < GG; g++) {
            float e = expf(w_s[g][tid] - mx);
            w_s[g][tid] = e;
            s += e;
        }
        float inv = 1.f / s;
#pragma unroll
        for (int g = 0; g < GG; g++) w_s[g][tid] *= inv;
    }
    __syncthreads();

    for (int idx = tid; idx < GG*DD; idx += 256) {
        int g  = idx >> 8;
        int d  = idx & 255;
        int h1 = d >> 5;
        int dd = d & 31;
        float acc = 0.f;
#pragma unroll
        for (int h2 = 0; h2 < 8; h2++)
            acc = fmaf(w_s[g][h1*8 + h2], buf[g][h2*32 + dd], acc);
        __nv_bfloat16 h, l;
        split_bf16(acc, h, l);
        g_ahi[base + idx] = h;
        g_alo[base + idx] = l;
    }
}

// ===========================================================================
// 4) residual + layernorm (ddof=1), warp-per-row (8 rows/CTA, no barriers)
// ===========================================================================
__global__ void __launch_bounds__(256) addnorm_kernel(const float* __restrict__ a,
                                                      const float* __restrict__ b,
                                                      const float* __restrict__ alpha,
                                                      const float* __restrict__ beta,
                                                      float* __restrict__ out,
                                                      int write_split)
{
    const int lane = threadIdx.x & 31;
    const int wrow = threadIdx.x >> 5;                    // 0..7
    const size_t row = (size_t)blockIdx.x * 8 + wrow;
    const int col0 = lane * 8;

    const float* ap = a + row * 256 + col0;
    const float* bp = b + row * 256 + col0;

    float4 a0 = *(const float4*)(ap + 0);
    float4 a1 = *(const float4*)(ap + 4);
    float4 b0 = *(const float4*)(bp + 0);
    float4 b1 = *(const float4*)(bp + 4);

    float z[8];
    z[0] = a0.x + b0.x; z[1] = a0.y + b0.y; z[2] = a0.z + b0.z; z[3] = a0.w + b0.w;
    z[4] = a1.x + b1.x; z[5] = a1.y + b1.y; z[6] = a1.z + b1.z; z[7] = a1.w + b1.w;

    float s = 0.f;
#pragma unroll
    for (int j = 0; j < 8; j++) s += z[j];
#pragma unroll
    for (int o = 16; o > 0; o >>= 1) s += __shfl_xor_sync(0xffffffffu, s, o);
    float mu = s * (1.f / 256.f);

    float dz[8];
    float s2 = 0.f;
#pragma unroll
    for (int j = 0; j < 8; j++) { dz[j] = z[j] - mu; s2 += dz[j] * dz[j]; }
#pragma unroll
    for (int o = 16; o > 0; o >>= 1) s2 += __shfl_xor_sync(0xffffffffu, s2, o);
    float inv = 1.f / (sqrtf(s2 * (1.f / 255.f)) + 1e-6f);

    float4 al0 = *(const float4*)(alpha + col0);
    float4 al1 = *(const float4*)(alpha + col0 + 4);
    float4 be0 = *(const float4*)(beta + col0);
    float4 be1 = *(const float4*)(beta + col0 + 4);
    float alr[8] = {al0.x, al0.y, al0.z, al0.w, al1.x, al1.y, al1.z, al1.w};
    float ber[8] = {be0.x, be0.y, be0.z, be0.w, be1.x, be1.y, be1.z, be1.w};

    float o[8];
#pragma unroll
    for (int j = 0; j < 8; j++) o[j] = alr[j] * dz[j] * inv + ber[j];

    float* op = out + row * 256 + col0;
    float4 o0, o1;
    o0.x = o[0]; o0.y = o[1]; o0.z = o[2]; o0.w = o[3];
    o1.x = o[4]; o1.y = o[5]; o1.z = o[6]; o1.w = o[7];
    *(float4*)(op + 0) = o0;
    *(float4*)(op + 4) = o1;

    if (write_split) {
        union { uint4 q; __nv_bfloat16 bb[8]; } hi, lo;
#pragma unroll
        for (int j = 0; j < 8; j++) {
            __nv_bfloat16 h, l;
            split_bf16(o[j], h, l);
            hi.bb[j] = h;
            lo.bb[j] = l;
        }
        *(uint4*)(g_ahi + row * 256 + col0) = hi.q;
        *(uint4*)(g_alo + row * 256 + col0) = lo.q;
    }
}

// ===========================================================================
extern "C" void kernel_launch(void* const* d_in, const int* in_sizes, int n_in,
                              void* d_out, int out_size)
{
    const float* x    = (const float*)d_in[0];
    const float* Adj  = (const float*)d_in[1];
    const float* Wq   = (const float*)d_in[2];
    const float* bq   = (const float*)d_in[3];
    const float* Wk   = (const float*)d_in[4];
    const float* bk   = (const float*)d_in[5];
    const float* Wv   = (const float*)d_in[6];
    const float* bv   = (const float*)d_in[7];
    const float* Wo   = (const float*)d_in[8];
    const float* bo   = (const float*)d_in[9];
    const float* Wfc  = (const float*)d_in[10];
    const float* bfc  = (const float*)d_in[11];
    const float* alpha= (const float*)d_in[12];
    const float* beta = (const float*)d_in[13];
    float* out = (float*)d_out;

    float *q, *k, *v;
    cudaGetSymbolAddress((void**)&q, g_buf1);
    cudaGetSymbolAddress((void**)&k, g_buf2);
    cudaGetSymbolAddress((void**)&v, g_buf3);
    __nv_bfloat16 *ahi, *alo, *whi, *wlo;
    cudaGetSymbolAddress((void**)&ahi, g_ahi);
    cudaGetSymbolAddress((void**)&alo, g_alo);
    cudaGetSymbolAddress((void**)&whi, g_whi);
    cudaGetSymbolAddress((void**)&wlo, g_wlo);

    cudaFuncSetAttribute(gemm2_kernel, cudaFuncAttributeMaxDynamicSharedMemorySize, GSMEM);

    dim3 ggrid(MROWS / 128, 2);

    // 0) split weights
    wprep_kernel<<<dim3(256, 5), 256>>>(Wq, Wk, Wv, Wo, Wfc);
    // 1) h = Adj @ x  -> split pair
    adj_kernel<<<BT, 256>>>(x, Adj);
    // 2) Q,K,V projections
    gemm2_kernel<<<ggrid, 256, GSMEM>>>(ahi, alo, whi + 0*DD*DD, wlo + 0*DD*DD, bq, q, 0);
    gemm2_kernel<<<ggrid, 256, GSMEM>>>(ahi, alo, whi + 1*DD*DD, wlo + 1*DD*DD, bk, k, 0);
    gemm2_kernel<<<ggrid, 256, GSMEM>>>(ahi, alo, whi + 2*DD*DD, wlo + 2*DD*DD, bv, v, 0);
    // 3) attention -> att split pair (h pair dead)
    attn_kernel<<<BT, 256>>>(q, k, v);
    // 4) x_att = att @ Wo^T + bo -> buf1 (Q dead)
    gemm2_kernel<<<ggrid, 256, GSMEM>>>(ahi, alo, whi + 3*DD*DD, wlo + 3*DD*DD, bo, q, 0);
    // 5) x1 = norm(x + x_att) -> buf2 fp32 + split pair (att pair dead)
    addnorm_kernel<<<MROWS / 8, 256>>>(x, q, alpha, beta, k, 1);
    // 6) fc = relu(x1 @ Wfc^T + bfc) -> buf3 (V dead)
    gemm2_kernel<<<ggrid, 256, GSMEM>>>(ahi, alo, whi + 4*DD*DD, wlo + 4*DD*DD, bfc, v, 1);
    // 7) out = norm(x1 + fc)
    addnorm_kernel<<<MROWS / 8, 256>>>(k, v, alpha, beta, out, 0);
}